// round 8
// baseline (speedup 1.0000x reference)
#include <cuda_runtime.h>
#include <cstdint>

#define L2E  1.4426950408889634f
#define LN2f 0.6931471805599453f

constexpr int S = 256, W = 32, T = 32, RS = 36;

__device__ float g_diff[64];
__device__ unsigned int g_ctr = 0;

static __device__ __forceinline__ float ex2f(float x){ float y; asm("ex2.approx.ftz.f32 %0, %1;" : "=f"(y) : "f"(x)); return y; }
static __device__ __forceinline__ float lg2f(float x){ float y; asm("lg2.approx.ftz.f32 %0, %1;" : "=f"(y) : "f"(x)); return y; }

__device__ __forceinline__ void cp_async16(uint32_t dst, const float* src){
    asm volatile("cp.async.cg.shared.global [%0], [%1], 16;\n" :: "r"(dst), "l"(src));
}
__device__ __forceinline__ void cp_commit(){ asm volatile("cp.async.commit_group;\n"); }
template<int N> __device__ __forceinline__ void cp_waitg(){ asm volatile("cp.async.wait_group %0;\n" :: "n"(N)); }

__device__ __forceinline__ void bar1(){ asm volatile("bar.sync 1, 128;" ::: "memory"); }
__device__ __forceinline__ void bar2(){ asm volatile("bar.sync 2, 128;" ::: "memory"); }

__global__ __launch_bounds__(256, 1)
void crf_kernel(const float* __restrict__ logits,
                const int*   __restrict__ tags,
                const int*   __restrict__ mask,
                const float* __restrict__ trans,
                const float* __restrict__ start_tr,
                const float* __restrict__ end_tr,
                float* __restrict__ out)
{
    __shared__ __align__(16) float sm_raw[4][1024];      // raw logit tiles [d][t]
    __shared__ __align__(16) float sm_eT[4][32 * RS];    // exp(emit) rotated: [t][slot]
    __shared__ __align__(16) float sm_R[32 * RS];        // linear ring, row per tag t
    __shared__ __align__(16) float sm_w[32];
    __shared__ float sm_trans[32 * 33];
    __shared__ float sm_num[3];
    __shared__ int   sm_ired[8];

    const int b    = blockIdx.x;
    const int tid  = threadIdx.x;
    const int warp = tid >> 5, lane = tid & 31;
    const float* lb = logits + (size_t)b * S * W * T;

    // ---- all warps: transitions to smem + sequence length ----
    for (int i = tid; i < T * T; i += 256)
        sm_trans[(i >> 5) * 33 + (i & 31)] = trans[i];
    {
        int mv = mask[b * S + tid];
        #pragma unroll
        for (int o = 16; o; o >>= 1) mv += __shfl_xor_sync(~0u, mv, o);
        if (lane == 0) sm_ired[warp] = mv;
    }
    __syncthreads();
    int len = 0;
    #pragma unroll
    for (int i = 0; i < 8; i++) len += sm_ired[i];

    if (warp == 4) return;

    // ================= numerator: warps 5,6,7 (runs concurrent with scan) =====
    if (warp >= 5) {
        const int nw = warp - 5;
        const int* tb = tags + (size_t)b * S * W;
        float acc = 0.f;
        for (int p = nw; p < len - 1; p += 3) {
            const int ptg = __ldg(&tb[p * 32 + lane]);
            float V = 0.f;   // V[t=lane] = sum_dd [ptg!=0]*trans[ptg][t]
            #pragma unroll
            for (int dd = 0; dd < 32; dd++) {
                const int pt = __shfl_sync(~0u, ptg, dd);
                if (pt != 0) V += sm_trans[pt * 33 + lane];
            }
            const int j  = p + 1 + lane;        // pair (j, d=lane), d<j always
            const int jv = (j < len) ? j : (len - 1);
            const int tg = __ldg(&tb[jv * 32 + lane]);
            const float vsel = __shfl_sync(~0u, V, tg);
            float e = 0.f;
            if (tg != 0) e = __ldg(&lb[(jv * 32 + lane) * 32 + tg]);
            if (j < len) acc += vsel + e;
        }
        if (nw == 0) {
            if (lane < len && lane < 32) {       // d == j diagonal (start terms)
                const int tgd = __ldg(&tb[lane * 33]);
                acc += __ldg(&start_tr[tgd]);
                if (tgd != 0) acc += __ldg(&lb[lane * 1056 + tgd]);
            }
            const int tgl = __ldg(&tb[(len - 1) * 32 + lane]);   // end terms
            if (tgl != 0) acc += __ldg(&end_tr[tgl]);
        }
        #pragma unroll
        for (int o = 16; o; o >>= 1) acc += __shfl_xor_sync(~0u, acc, o);
        if (lane == 0) sm_num[nw] = acc;
        bar2();
        return;
    }

    // ================= warps 0..3: scan pipeline ==========================
    const uint32_t rawb = (uint32_t)__cvta_generic_to_shared(&sm_raw[0][0]);

    float E[32];
    float rho = 0.f, w = 1.f, end2 = 0.f;
    float* Rr = sm_R + lane * RS;

    if (warp == 0) {
        // scanner prologue: E columns, ring init
        #pragma unroll
        for (int k = 0; k < 32; k++)
            E[k] = ex2f(sm_trans[k * 33 + lane] * L2E);   // exp(trans[k][lane])
        end2 = end_tr[lane] * L2E;
        #pragma unroll
        for (int c = 0; c < 9; c++)
            *(float4*)(Rr + 4 * c) = make_float4(0.f, 0.f, 0.f, 0.f);
        Rr[31] = ex2f(start_tr[lane] * L2E);              // start preload, rho0=0
    } else {
        // producer prologue: raw tiles 0..3, convert tiles 0,1
        const int gid = (warp - 1) * 32 + lane;
        for (int tt = 0; tt < 4; tt++) {
            if (tt < len) {
                const float* src = lb + (size_t)tt * 1024;
                const uint32_t dsl = rawb + (uint32_t)(tt * 4096);
                for (int c = gid; c < 256; c += 96)
                    cp_async16(dsl + (uint32_t)(c * 16), src + c * 4);
            }
            cp_commit();
        }
        cp_waitg<2>();
        for (int tt = 0; tt < 2; tt++) {
            if (tt < len) {
                const float* raw = sm_raw[tt];
                float* dst = sm_eT[tt];
                for (int sl = warp - 1; sl < 32; sl += 3) {
                    const int d = (tt - 1 - sl) & 31;
                    dst[lane * RS + sl] = ex2f(raw[d * 32 + lane] * L2E);
                }
            }
        }
    }

    for (int j = 0; j < len; j++) {
        bar1();
        if (warp == 0) {
            if ((j & 3) == 0 && j > 0) {
                // epoch rescale using previous step's w
                float wm = w;
                #pragma unroll
                for (int o = 1; o < 32; o <<= 1)
                    wm = fmaxf(wm, __shfl_xor_sync(0xffffffffu, wm, o));
                const float delta = lg2f(wm);
                const float f = ex2f(-delta);
                rho += delta;
                #pragma unroll
                for (int c = 0; c < 8; c++) {
                    float4 r4 = *(float4*)(Rr + 4 * c);
                    r4.x *= f; r4.y *= f; r4.z *= f; r4.w *= f;
                    *(float4*)(Rr + 4 * c) = r4;
                }
            }
            // stage 1: w[t] = sum_sl eT[t][sl] * R[t][sl]
            const float* eTp = sm_eT[j & 3] + lane * RS;
            float a0 = 0.f, a1 = 0.f, a2 = 0.f, a3 = 0.f;
            #pragma unroll
            for (int c = 0; c < 8; c++) {
                const float4 e4 = *(const float4*)(eTp + 4 * c);
                const float4 r4 = *(const float4*)(Rr + 4 * c);
                a0 = fmaf(e4.x, r4.x, a0);
                a1 = fmaf(e4.y, r4.y, a1);
                a2 = fmaf(e4.z, r4.z, a2);
                a3 = fmaf(e4.w, r4.w, a3);
            }
            w = (a0 + a1) + (a2 + a3);
            sm_w[lane] = w;
            __syncwarp();
            // stage 2: D[t] = sum_k w[k] * exp(trans[k][t])
            float D0 = 0.f, D1 = 0.f, D2 = 0.f, D3 = 0.f;
            #pragma unroll
            for (int c = 0; c < 8; c++) {
                const float4 w4 = *(const float4*)(sm_w + 4 * c);
                D0 = fmaf(w4.x, E[4 * c + 0], D0);
                D1 = fmaf(w4.y, E[4 * c + 1], D1);
                D2 = fmaf(w4.z, E[4 * c + 2], D2);
                D3 = fmaf(w4.w, E[4 * c + 3], D3);
            }
            Rr[j & 31] = (D0 + D1) + (D2 + D3);
        } else {
            // producers: issue raw j+4, ensure raw j+2, convert -> eT[j+2]
            const int gid = (warp - 1) * 32 + lane;
            const int J2 = j + 4;
            if (J2 < len) {
                const float* src = lb + (size_t)J2 * 1024;
                const uint32_t dsl = rawb + (uint32_t)((J2 & 3) * 4096);
                for (int c = gid; c < 256; c += 96)
                    cp_async16(dsl + (uint32_t)(c * 16), src + c * 4);
            }
            cp_commit();
            cp_waitg<2>();
            const int J = j + 2;
            if (J < len) {
                const float* raw = sm_raw[J & 3];
                float* dst = sm_eT[J & 3];
                for (int sl = warp - 1; sl < 32; sl += 3) {
                    const int d = (J - 1 - sl) & 31;
                    dst[lane * RS + sl] = ex2f(raw[d * 32 + lane] * L2E);
                }
            }
        }
    }

    if (warp != 0) return;     // producers done

    // ---------------- scanner finalize ----------------
    bar2();                    // numerator partials ready
    const float v = rho + lg2f(w) + end2;      // alpha_last[t]*log2e + end
    float m = v;
    #pragma unroll
    for (int o = 1; o < 32; o <<= 1)
        m = fmaxf(m, __shfl_xor_sync(0xffffffffu, m, o));
    float s2 = ex2f(v - m);
    #pragma unroll
    for (int o = 1; o < 32; o <<= 1)
        s2 += __shfl_xor_sync(0xffffffffu, s2, o);

    const float num = sm_num[0] + sm_num[1] + sm_num[2];
    unsigned int done = 0;
    if (lane == 0) {
        const float den = LN2f * (m + lg2f(s2));
        out[1 + b] = num;
        g_diff[b]  = num - den;
        __threadfence();
        done = (atomicAdd(&g_ctr, 1u) == 63u) ? 1u : 0u;
    }
    done = __shfl_sync(~0u, done, 0);
    if (done) {
        float x = __ldcg(&g_diff[lane]) + __ldcg(&g_diff[lane + 32]);
        #pragma unroll
        for (int o = 16; o; o >>= 1) x += __shfl_xor_sync(~0u, x, o);
        if (lane == 0) {
            out[0] = x * (1.f / 64.f);
            g_ctr = 0;                      // reset for next graph replay
        }
    }
}

extern "C" void kernel_launch(void* const* d_in, const int* in_sizes, int n_in,
                              void* d_out, int out_size)
{
    const float* logits = (const float*)d_in[0];
    const int*   tags   = (const int*)d_in[1];
    const int*   mask   = (const int*)d_in[2];
    const float* trans  = (const float*)d_in[3];
    const float* st     = (const float*)d_in[4];
    const float* en     = (const float*)d_in[5];
    float*       out    = (float*)d_out;

    crf_kernel<<<64, 256>>>(logits, tags, mask, trans, st, en, out);
}

// round 9
// speedup vs baseline: 1.0660x; 1.0660x over previous
#include <cuda_runtime.h>
#include <cstdint>

#define L2E  1.4426950408889634f
#define LN2f 0.6931471805599453f

constexpr int S = 256, W = 32, T = 32, RS = 36, DEP = 8;

__device__ float g_diff[64];
__device__ unsigned int g_ctr = 0;

static __device__ __forceinline__ float ex2f(float x){ float y; asm("ex2.approx.ftz.f32 %0, %1;" : "=f"(y) : "f"(x)); return y; }
static __device__ __forceinline__ float lg2f(float x){ float y; asm("lg2.approx.ftz.f32 %0, %1;" : "=f"(y) : "f"(x)); return y; }

__device__ __forceinline__ void cp_async16(uint32_t dst, const float* src){
    asm volatile("cp.async.cg.shared.global [%0], [%1], 16;\n" :: "r"(dst), "l"(src));
}
__device__ __forceinline__ void cp_commit(){ asm volatile("cp.async.commit_group;\n"); }
template<int N> __device__ __forceinline__ void cp_waitg(){ asm volatile("cp.async.wait_group %0;\n" :: "n"(N)); }

__device__ __forceinline__ int ld_acq(const int* p){
    int v;
    asm volatile("ld.acquire.cta.shared.b32 %0, [%1];"
                 : "=r"(v) : "r"((uint32_t)__cvta_generic_to_shared(p)) : "memory");
    return v;
}
__device__ __forceinline__ void st_rel(int* p, int v){
    asm volatile("st.release.cta.shared.b32 [%0], %1;"
                 :: "r"((uint32_t)__cvta_generic_to_shared(p)), "r"(v) : "memory");
}

__device__ __forceinline__ void bar2(){ asm volatile("bar.sync 2, 128;" ::: "memory"); }

extern __shared__ float dynsm[];   // eT ring [DEP][32*RS] then raw [3][2][1024]

__global__ __launch_bounds__(256, 1)
void crf_kernel(const float* __restrict__ logits,
                const int*   __restrict__ tags,
                const int*   __restrict__ mask,
                const float* __restrict__ trans,
                const float* __restrict__ start_tr,
                const float* __restrict__ end_tr,
                float* __restrict__ out)
{
    __shared__ float sm_trans[32 * 33];
    __shared__ int   sm_flag[DEP];
    __shared__ int   sm_prog;
    __shared__ int   sm_ired[8];
    __shared__ float sm_num[3];

    float* eT  = dynsm;
    float* raw = dynsm + DEP * 32 * RS;

    const int b    = blockIdx.x;
    const int tid  = threadIdx.x;
    const int warp = tid >> 5, lane = tid & 31;
    const float* lb = logits + (size_t)b * S * W * T;

    for (int i = tid; i < T * T; i += 256)
        sm_trans[(i >> 5) * 33 + (i & 31)] = trans[i];
    if (tid < DEP) sm_flag[tid] = -1;
    if (tid == 0)  sm_prog = 0;
    {
        int mv = mask[b * S + tid];
        #pragma unroll
        for (int o = 16; o; o >>= 1) mv += __shfl_xor_sync(~0u, mv, o);
        if (lane == 0) sm_ired[warp] = mv;
    }
    __syncthreads();
    int len = 0;
    #pragma unroll
    for (int i = 0; i < 8; i++) len += sm_ired[i];

    if (warp == 4) return;

    // ---------------- numerator: warps 5,6,7 ----------------
    if (warp >= 5) {
        const int nw = warp - 5;
        const int* tb = tags + (size_t)b * S * W;
        float acc = 0.f;
        for (int p = nw; p < len - 1; p += 3) {
            const int ptg = __ldg(&tb[p * 32 + lane]);
            float V = 0.f;
            #pragma unroll
            for (int dd = 0; dd < 32; dd++) {
                const int pt = __shfl_sync(~0u, ptg, dd);
                if (pt != 0) V += sm_trans[pt * 33 + lane];
            }
            const int j  = p + 1 + lane;
            const int jv = (j < len) ? j : (len - 1);
            const int tg = __ldg(&tb[jv * 32 + lane]);
            const float vsel = __shfl_sync(~0u, V, tg);
            float e = 0.f;
            if (tg != 0) e = __ldg(&lb[(jv * 32 + lane) * 32 + tg]);
            if (j < len) acc += vsel + e;
        }
        if (nw == 0) {
            if (lane < len) {
                const int tgd = __ldg(&tb[lane * 33]);
                acc += __ldg(&start_tr[tgd]);
                if (tgd != 0) acc += __ldg(&lb[lane * 1056 + tgd]);
            }
            const int tgl = __ldg(&tb[(len - 1) * 32 + lane]);
            if (tgl != 0) acc += __ldg(&end_tr[tgl]);
        }
        #pragma unroll
        for (int o = 16; o; o >>= 1) acc += __shfl_xor_sync(~0u, acc, o);
        if (lane == 0) sm_num[nw] = acc;
        bar2();
        return;
    }

    // ---------------- producers: warps 1,2,3 ----------------
    if (warp != 0) {
        const int pw = warp - 1;
        float* myraw = raw + pw * 2048;
        const uint32_t rawu = (uint32_t)__cvta_generic_to_shared(myraw);
        #pragma unroll
        for (int k = 0; k < 2; k++) {
            const int Jk = pw + 3 * k;
            if (Jk < len) {
                const float* src = lb + (size_t)Jk * 1024;
                const uint32_t dst = rawu + (uint32_t)(k * 4096);
                #pragma unroll
                for (int c = 0; c < 8; c++)
                    cp_async16(dst + (uint32_t)((lane + 32 * c) * 16),
                               src + (lane + 32 * c) * 4);
            }
            cp_commit();
        }
        int pb = 0;
        for (int J = pw; J < len; J += 3, pb ^= 1) {
            cp_waitg<1>();
            while (J >= ld_acq(&sm_prog) + DEP) ;
            const float* rb = myraw + pb * 1024;
            float* dst = eT + (J & 7) * (32 * RS) + lane * RS;
            #pragma unroll
            for (int m = 0; m < 8; m++) {
                float4 v;
                v.x = ex2f(rb[(((J - 1 - (4 * m + 0)) & 31) << 5) + lane] * L2E);
                v.y = ex2f(rb[(((J - 1 - (4 * m + 1)) & 31) << 5) + lane] * L2E);
                v.z = ex2f(rb[(((J - 1 - (4 * m + 2)) & 31) << 5) + lane] * L2E);
                v.w = ex2f(rb[(((J - 1 - (4 * m + 3)) & 31) << 5) + lane] * L2E);
                *(float4*)(dst + 4 * m) = v;
            }
            st_rel(&sm_flag[J & 7], J);
            const int Jn = J + 6;
            if (Jn < len) {
                const float* src = lb + (size_t)Jn * 1024;
                const uint32_t d2 = rawu + (uint32_t)(pb * 4096);
                #pragma unroll
                for (int c = 0; c < 8; c++)
                    cp_async16(d2 + (uint32_t)((lane + 32 * c) * 16),
                               src + (lane + 32 * c) * 4);
            }
            cp_commit();
        }
        return;
    }

    // ---------------- scanner: warp 0 ----------------
    float E[32];
    #pragma unroll
    for (int k = 0; k < 32; k++)
        E[k] = ex2f(sm_trans[k * 33 + lane] * L2E);
    const float end2 = end_tr[lane] * L2E;

    float R[32];
    #pragma unroll
    for (int sl = 0; sl < 31; sl++) R[sl] = 0.f;
    R[31] = ex2f(start_tr[lane] * L2E);

    float rho = 0.f, w = 1.f;

    for (int jb = 0; jb < len; jb += 32) {
        #pragma unroll
        for (int sl = 0; sl < 32; sl++) {
            const int j = jb + sl;
            if (j < len) {
                while (ld_acq(&sm_flag[sl & 7]) != j) ;
                if ((sl & 3) == 0 && j > 0) {
                    float wm = w;
                    #pragma unroll
                    for (int o = 1; o < 32; o <<= 1)
                        wm = fmaxf(wm, __shfl_xor_sync(0xffffffffu, wm, o));
                    const float delta = lg2f(wm);
                    const float f = ex2f(-delta);
                    rho += delta;
                    #pragma unroll
                    for (int k = 0; k < 32; k++) R[k] *= f;
                }
                const float* ep = eT + (sl & 7) * (32 * RS) + lane * RS;
                float a0 = 0.f, a1 = 0.f, a2 = 0.f, a3 = 0.f;
                #pragma unroll
                for (int m = 0; m < 8; m++) {
                    const float4 e4 = *(const float4*)(ep + 4 * m);
                    a0 = fmaf(e4.x, R[4 * m + 0], a0);
                    a1 = fmaf(e4.y, R[4 * m + 1], a1);
                    a2 = fmaf(e4.z, R[4 * m + 2], a2);
                    a3 = fmaf(e4.w, R[4 * m + 3], a3);
                }
                w = (a0 + a1) + (a2 + a3);
                float D0 = 0.f, D1 = 0.f, D2 = 0.f, D3 = 0.f;
                #pragma unroll
                for (int k = 0; k < 32; k++) {
                    const float wk = __shfl_sync(0xffffffffu, w, k);
                    if      ((k & 3) == 0) D0 = fmaf(wk, E[k], D0);
                    else if ((k & 3) == 1) D1 = fmaf(wk, E[k], D1);
                    else if ((k & 3) == 2) D2 = fmaf(wk, E[k], D2);
                    else                   D3 = fmaf(wk, E[k], D3);
                }
                R[sl] = (D0 + D1) + (D2 + D3);
                st_rel(&sm_prog, j + 1);
            }
        }
    }

    bar2();
    const float v = rho + lg2f(w) + end2;
    float m = v;
    #pragma unroll
    for (int o = 1; o < 32; o <<= 1)
        m = fmaxf(m, __shfl_xor_sync(0xffffffffu, m, o));
    float s2 = ex2f(v - m);
    #pragma unroll
    for (int o = 1; o < 32; o <<= 1)
        s2 += __shfl_xor_sync(0xffffffffu, s2, o);

    const float num = sm_num[0] + sm_num[1] + sm_num[2];
    unsigned int done = 0;
    if (lane == 0) {
        const float den = LN2f * (m + lg2f(s2));
        out[1 + b] = num;
        g_diff[b]  = num - den;
        __threadfence();
        done = (atomicAdd(&g_ctr, 1u) == 63u) ? 1u : 0u;
    }
    done = __shfl_sync(~0u, done, 0);
    if (done) {
        float x = __ldcg(&g_diff[lane]) + __ldcg(&g_diff[lane + 32]);
        #pragma unroll
        for (int o = 16; o; o >>= 1) x += __shfl_xor_sync(~0u, x, o);
        if (lane == 0) {
            out[0] = x * (1.f / 64.f);
            g_ctr = 0;
        }
    }
}

extern "C" void kernel_launch(void* const* d_in, const int* in_sizes, int n_in,
                              void* d_out, int out_size)
{
    const float* logits = (const float*)d_in[0];
    const int*   tags   = (const int*)d_in[1];
    const int*   mask   = (const int*)d_in[2];
    const float* trans  = (const float*)d_in[3];
    const float* st     = (const float*)d_in[4];
    const float* en     = (const float*)d_in[5];
    float*       out    = (float*)d_out;

    const int dyn = (DEP * 32 * RS + 3 * 2 * 1024) * 4;   // 61440 B
    cudaFuncSetAttribute(crf_kernel, cudaFuncAttributeMaxDynamicSharedMemorySize, dyn);
    crf_kernel<<<64, 256, dyn>>>(logits, tags, mask, trans, st, en, out);
}

// round 11
// speedup vs baseline: 1.7335x; 1.6261x over previous
#include <cuda_runtime.h>
#include <cstdint>

#define L2E  1.4426950408889634f
#define LN2f 0.6931471805599453f

constexpr int S = 256, W = 32, T = 32, RS = 36;
constexpr int DEP = 16;          // eT ring depth (tiles)
constexpr int RAWB = 4;          // raw buffers per producer warp

__device__ float g_diff[64];
__device__ unsigned int g_ctr = 0;

static __device__ __forceinline__ float ex2f(float x){ float y; asm("ex2.approx.ftz.f32 %0, %1;" : "=f"(y) : "f"(x)); return y; }
static __device__ __forceinline__ float lg2f(float x){ float y; asm("lg2.approx.ftz.f32 %0, %1;" : "=f"(y) : "f"(x)); return y; }

__device__ __forceinline__ void cp_async16(uint32_t dst, const float* src){
    asm volatile("cp.async.cg.shared.global [%0], [%1], 16;\n" :: "r"(dst), "l"(src));
}
__device__ __forceinline__ void cp_commit(){ asm volatile("cp.async.commit_group;\n"); }
template<int N> __device__ __forceinline__ void cp_waitg(){ asm volatile("cp.async.wait_group %0;\n" :: "n"(N)); }

__device__ __forceinline__ int ld_acq(const int* p){
    int v;
    asm volatile("ld.acquire.cta.shared.b32 %0, [%1];"
                 : "=r"(v) : "r"((uint32_t)__cvta_generic_to_shared(p)) : "memory");
    return v;
}
__device__ __forceinline__ void st_rel(int* p, int v){
    asm volatile("st.release.cta.shared.b32 [%0], %1;"
                 :: "r"((uint32_t)__cvta_generic_to_shared(p)), "r"(v) : "memory");
}

__device__ __forceinline__ void bar2(){ asm volatile("bar.sync 2, 128;" ::: "memory"); }

extern __shared__ float dynsm[];   // [DEP][32*RS] eT ring, then [3][RAWB][1024] raw

__global__ __launch_bounds__(256, 1)
void crf_kernel(const float* __restrict__ logits,
                const int*   __restrict__ tags,
                const int*   __restrict__ mask,
                const float* __restrict__ trans,
                const float* __restrict__ start_tr,
                const float* __restrict__ end_tr,
                float* __restrict__ out)
{
    __shared__ float sm_trans[32 * 33];
    __shared__ int   sm_flag[DEP];
    __shared__ int   sm_prog;
    __shared__ int   sm_ired[8];
    __shared__ float sm_num[3];

    float* eT  = dynsm;
    float* raw = dynsm + DEP * 32 * RS;

    const int b    = blockIdx.x;
    const int tid  = threadIdx.x;
    const int warp = tid >> 5, lane = tid & 31;
    const float* lb = logits + (size_t)b * S * W * T;

    for (int i = tid; i < T * T; i += 256)
        sm_trans[(i >> 5) * 33 + (i & 31)] = trans[i];
    if (tid < DEP) sm_flag[tid] = -1;
    if (tid == 0)  sm_prog = 0;
    {
        int mv = mask[b * S + tid];
        #pragma unroll
        for (int o = 16; o; o >>= 1) mv += __shfl_xor_sync(~0u, mv, o);
        if (lane == 0) sm_ired[warp] = mv;
    }
    __syncthreads();
    int len = 0;
    #pragma unroll
    for (int i = 0; i < 8; i++) len += sm_ired[i];

    if (warp == 4) return;                 // SMSP0 stays exclusive to scanner

    // ================= numerator: warps 5,6,7 (concurrent) =================
    if (warp >= 5) {
        const int nw = warp - 5;
        const int* tb = tags + (size_t)b * S * W;
        float acc = 0.f;
        for (int p = nw; p < len - 1; p += 3) {
            const int ptg = __ldg(&tb[p * 32 + lane]);
            float V = 0.f;                        // V[t=lane]
            #pragma unroll
            for (int dd = 0; dd < 32; dd++) {
                const int pt = __shfl_sync(~0u, ptg, dd);
                if (pt != 0) V += sm_trans[pt * 33 + lane];
            }
            const int j  = p + 1 + lane;
            const int jv = (j < len) ? j : (len - 1);
            const int tg = __ldg(&tb[jv * 32 + lane]);
            const float vsel = __shfl_sync(~0u, V, tg);
            float e = 0.f;
            if (tg != 0) e = __ldg(&lb[(jv * 32 + lane) * 32 + tg]);
            if (j < len) acc += vsel + e;
        }
        if (nw == 0) {
            if (lane < len) {                     // d == j diagonal (start)
                const int tgd = __ldg(&tb[lane * 33]);
                acc += __ldg(&start_tr[tgd]);
                if (tgd != 0) acc += __ldg(&lb[lane * 1056 + tgd]);
            }
            const int tgl = __ldg(&tb[(len - 1) * 32 + lane]);
            if (tgl != 0) acc += __ldg(&end_tr[tgl]);
        }
        #pragma unroll
        for (int o = 16; o; o >>= 1) acc += __shfl_xor_sync(~0u, acc, o);
        if (lane == 0) sm_num[nw] = acc;
        bar2();
        return;
    }

    // ================= producers: warps 1,2,3 (deep free-running) ==========
    if (warp != 0) {
        const int pw = warp - 1;                  // 0..2; warp pw owns tiles pw+3k
        float* myraw = raw + pw * (RAWB * 1024);
        const uint32_t rawu = (uint32_t)__cvta_generic_to_shared(myraw);
        // prologue: issue RAWB tiles (one group each)
        #pragma unroll
        for (int k = 0; k < RAWB; k++) {
            const int Jk = pw + 3 * k;
            if (Jk < len) {
                const float* src = lb + (size_t)Jk * 1024;
                const uint32_t dst = rawu + (uint32_t)(k * 4096);
                #pragma unroll
                for (int c = 0; c < 8; c++)
                    cp_async16(dst + (uint32_t)((lane + 32 * c) * 16),
                               src + (lane + 32 * c) * 4);
            }
            cp_commit();
        }
        int k = 0;
        for (int J = pw; J < len; J += 3, k = (k + 1) & (RAWB - 1)) {
            cp_waitg<RAWB - 1>();                 // oldest group (tile J) landed
            while (J >= ld_acq(&sm_prog) + DEP) ; // ring backpressure
            const float* rb = myraw + k * 1024;
            float* dst = eT + (J & (DEP - 1)) * (32 * RS) + lane * RS;
            #pragma unroll
            for (int m = 0; m < 8; m++) {
                float4 v;
                v.x = ex2f(rb[(((J - 1 - (4 * m + 0)) & 31) << 5) + lane] * L2E);
                v.y = ex2f(rb[(((J - 1 - (4 * m + 1)) & 31) << 5) + lane] * L2E);
                v.z = ex2f(rb[(((J - 1 - (4 * m + 2)) & 31) << 5) + lane] * L2E);
                v.w = ex2f(rb[(((J - 1 - (4 * m + 3)) & 31) << 5) + lane] * L2E);
                *(float4*)(dst + 4 * m) = v;
            }
            st_rel(&sm_flag[J & (DEP - 1)], J);
            const int Jn = J + 3 * RAWB;          // refill the freed buffer
            if (Jn < len) {
                const float* src = lb + (size_t)Jn * 1024;
                const uint32_t d2 = rawu + (uint32_t)(k * 4096);
                #pragma unroll
                for (int c = 0; c < 8; c++)
                    cp_async16(d2 + (uint32_t)((lane + 32 * c) * 16),
                               src + (lane + 32 * c) * 4);
            }
            cp_commit();
        }
        return;
    }

    // ================= scanner: warp 0 =====================================
    float E[32];
    #pragma unroll
    for (int kk = 0; kk < 32; kk++)
        E[kk] = ex2f(sm_trans[kk * 33 + lane] * L2E);
    const float end2 = end_tr[lane] * L2E;

    float R[32];
    #pragma unroll
    for (int sl = 0; sl < 31; sl++) R[sl] = 0.f;
    R[31] = ex2f(start_tr[lane] * L2E);           // start preload (rho0 = 0)

    float rho = 0.f, w = 1.f;

    for (int jb = 0; jb < len; jb += 32) {
        #pragma unroll
        for (int sl = 0; sl < 32; sl++) {
            const int j = jb + sl;
            if (j < len) {
                while (ld_acq(&sm_flag[sl & (DEP - 1)]) != j) ;
                if ((sl & 3) == 0 && j > 0) {     // epoch rescale
                    float wm = w;
                    #pragma unroll
                    for (int o = 1; o < 32; o <<= 1)
                        wm = fmaxf(wm, __shfl_xor_sync(0xffffffffu, wm, o));
                    const float delta = lg2f(wm);
                    const float f = ex2f(-delta);
                    rho += delta;
                    #pragma unroll
                    for (int kk = 0; kk < 32; kk++) R[kk] *= f;
                }
                const float* ep = eT + (sl & (DEP - 1)) * (32 * RS) + lane * RS;
                float a0 = 0.f, a1 = 0.f, a2 = 0.f, a3 = 0.f;
                #pragma unroll
                for (int m = 0; m < 8; m++) {
                    const float4 e4 = *(const float4*)(ep + 4 * m);
                    a0 = fmaf(e4.x, R[4 * m + 0], a0);
                    a1 = fmaf(e4.y, R[4 * m + 1], a1);
                    a2 = fmaf(e4.z, R[4 * m + 2], a2);
                    a3 = fmaf(e4.w, R[4 * m + 3], a3);
                }
                w = (a0 + a1) + (a2 + a3);
                float D0 = 0.f, D1 = 0.f, D2 = 0.f, D3 = 0.f;
                #pragma unroll
                for (int kk = 0; kk < 32; kk++) {
                    const float wk = __shfl_sync(0xffffffffu, w, kk);
                    if      ((kk & 3) == 0) D0 = fmaf(wk, E[kk], D0);
                    else if ((kk & 3) == 1) D1 = fmaf(wk, E[kk], D1);
                    else if ((kk & 3) == 2) D2 = fmaf(wk, E[kk], D2);
                    else                    D3 = fmaf(wk, E[kk], D3);
                }
                R[sl] = (D0 + D1) + (D2 + D3);
                if ((sl & 7) == 7)                // amortized progress publish
                    st_rel(&sm_prog, j + 1);
            }
        }
    }

    // ---------------- finalize ----------------
    bar2();                                       // numerator partials ready
    const float v = rho + lg2f(w) + end2;
    float m = v;
    #pragma unroll
    for (int o = 1; o < 32; o <<= 1)
        m = fmaxf(m, __shfl_xor_sync(0xffffffffu, m, o));
    float s2 = ex2f(v - m);
    #pragma unroll
    for (int o = 1; o < 32; o <<= 1)
        s2 += __shfl_xor_sync(0xffffffffu, s2, o);

    const float num = sm_num[0] + sm_num[1] + sm_num[2];
    unsigned int done = 0;
    if (lane == 0) {
        const float den = LN2f * (m + lg2f(s2));
        out[1 + b] = num;
        g_diff[b]  = num - den;
        __threadfence();
        done = (atomicAdd(&g_ctr, 1u) == 63u) ? 1u : 0u;
    }
    done = __shfl_sync(~0u, done, 0);
    if (done) {
        float x = __ldcg(&g_diff[lane]) + __ldcg(&g_diff[lane + 32]);
        #pragma unroll
        for (int o = 16; o; o >>= 1) x += __shfl_xor_sync(~0u, x, o);
        if (lane == 0) {
            out[0] = x * (1.f / 64.f);
            g_ctr = 0;
        }
    }
}

extern "C" void kernel_launch(void* const* d_in, const int* in_sizes, int n_in,
                              void* d_out, int out_size)
{
    const float* logits = (const float*)d_in[0];
    const int*   tags   = (const int*)d_in[1];
    const int*   mask   = (const int*)d_in[2];
    const float* trans  = (const float*)d_in[3];
    const float* st     = (const float*)d_in[4];
    const float* en     = (const float*)d_in[5];
    float*       out    = (float*)d_out;

    const int dyn = (DEP * 32 * RS + 3 * RAWB * 1024) * 4;   // 122880 B
    cudaFuncSetAttribute(crf_kernel, cudaFuncAttributeMaxDynamicSharedMemorySize, dyn);
    crf_kernel<<<64, 256, dyn>>>(logits, tags, mask, trans, st, en, out);
}

// round 14
// speedup vs baseline: 1.8825x; 1.0860x over previous
#include <cuda_runtime.h>
#include <cstdint>

#define L2E  1.4426950408889634f
#define LN2f 0.6931471805599453f

constexpr int S = 256, W = 32, T = 32, RS = 36;
constexpr int DEP  = 16;         // eT ring depth (tiles)
constexpr int RAWB = 6;          // raw buffers per producer warp
constexpr int NPROD = 4;         // producer warps (1..4)

__device__ float g_diff[64];
__device__ unsigned int g_ctr = 0;

static __device__ __forceinline__ float ex2f(float x){ float y; asm("ex2.approx.ftz.f32 %0, %1;" : "=f"(y) : "f"(x)); return y; }
static __device__ __forceinline__ float lg2f(float x){ float y; asm("lg2.approx.ftz.f32 %0, %1;" : "=f"(y) : "f"(x)); return y; }

__device__ __forceinline__ void cp_async16(uint32_t dst, const float* src){
    asm volatile("cp.async.cg.shared.global [%0], [%1], 16;\n" :: "r"(dst), "l"(src));
}
__device__ __forceinline__ void cp_commit(){ asm volatile("cp.async.commit_group;\n"); }
template<int N> __device__ __forceinline__ void cp_waitg(){ asm volatile("cp.async.wait_group %0;\n" :: "n"(N)); }

__device__ __forceinline__ int ld_acq(const int* p){
    int v;
    asm volatile("ld.acquire.cta.shared.b32 %0, [%1];"
                 : "=r"(v) : "r"((uint32_t)__cvta_generic_to_shared(p)) : "memory");
    return v;
}
__device__ __forceinline__ void st_rel(int* p, int v){
    asm volatile("st.release.cta.shared.b32 [%0], %1;"
                 :: "r"((uint32_t)__cvta_generic_to_shared(p)), "r"(v) : "memory");
}

__device__ __forceinline__ void bar2(){ asm volatile("bar.sync 2, 128;" ::: "memory"); }

extern __shared__ float dynsm[];   // [DEP][32*RS] eT ring, then [NPROD][RAWB][1024] raw

__global__ __launch_bounds__(256, 1)
void crf_kernel(const float* __restrict__ logits,
                const int*   __restrict__ tags,
                const int*   __restrict__ mask,
                const float* __restrict__ trans,
                const float* __restrict__ start_tr,
                const float* __restrict__ end_tr,
                float* __restrict__ out)
{
    __shared__ float sm_trans[32 * 33];
    __shared__ __align__(16) float sm_w[32];
    __shared__ int   sm_flag[DEP];
    __shared__ int   sm_prog;
    __shared__ int   sm_ired[8];
    __shared__ float sm_num[3];

    float* eT  = dynsm;
    float* raw = dynsm + DEP * 32 * RS;

    const int b    = blockIdx.x;
    const int tid  = threadIdx.x;
    const int warp = tid >> 5, lane = tid & 31;
    const float* lb = logits + (size_t)b * S * W * T;

    for (int i = tid; i < T * T; i += 256)
        sm_trans[(i >> 5) * 33 + (i & 31)] = trans[i];
    if (tid < DEP) sm_flag[tid] = -1;
    if (tid == 0)  sm_prog = 0;
    {
        int mv = mask[b * S + tid];
        #pragma unroll
        for (int o = 16; o; o >>= 1) mv += __shfl_xor_sync(~0u, mv, o);
        if (lane == 0) sm_ired[warp] = mv;
    }
    __syncthreads();
    int len = 0;
    #pragma unroll
    for (int i = 0; i < 8; i++) len += sm_ired[i];

    // ================= numerator: warps 5,6,7 (concurrent) =================
    if (warp >= 5) {
        const int nw = warp - 5;
        const int* tb = tags + (size_t)b * S * W;
        float acc = 0.f;
        for (int p = nw; p < len - 1; p += 3) {
            const int ptg = __ldg(&tb[p * 32 + lane]);
            float V = 0.f;                        // V[t=lane]
            #pragma unroll
            for (int dd = 0; dd < 32; dd++) {
                const int pt = __shfl_sync(~0u, ptg, dd);
                if (pt != 0) V += sm_trans[pt * 33 + lane];
            }
            const int j  = p + 1 + lane;
            const int jv = (j < len) ? j : (len - 1);
            const int tg = __ldg(&tb[jv * 32 + lane]);
            const float vsel = __shfl_sync(~0u, V, tg);
            float e = 0.f;
            if (tg != 0) e = __ldg(&lb[(jv * 32 + lane) * 32 + tg]);
            if (j < len) acc += vsel + e;
        }
        if (nw == 0) {
            if (lane < len) {                     // d == j diagonal (start)
                const int tgd = __ldg(&tb[lane * 33]);
                acc += __ldg(&start_tr[tgd]);
                if (tgd != 0) acc += __ldg(&lb[lane * 1056 + tgd]);
            }
            const int tgl = __ldg(&tb[(len - 1) * 32 + lane]);
            if (tgl != 0) acc += __ldg(&end_tr[tgl]);
        }
        #pragma unroll
        for (int o = 16; o; o >>= 1) acc += __shfl_xor_sync(~0u, acc, o);
        if (lane == 0) sm_num[nw] = acc;
        bar2();
        return;
    }

    // ================= producers: warps 1..4 (deep free-running) ===========
    if (warp != 0) {
        const int pw = warp - 1;                  // 0..3; owns tiles pw + 4k
        float* myraw = raw + pw * (RAWB * 1024);
        const uint32_t rawu = (uint32_t)__cvta_generic_to_shared(myraw);
        #pragma unroll
        for (int k = 0; k < RAWB; k++) {          // prologue: RAWB groups
            const int Jk = pw + NPROD * k;
            if (Jk < len) {
                const float* src = lb + (size_t)Jk * 1024;
                const uint32_t dst = rawu + (uint32_t)(k * 4096);
                #pragma unroll
                for (int c = 0; c < 8; c++)
                    cp_async16(dst + (uint32_t)((lane + 32 * c) * 16),
                               src + (lane + 32 * c) * 4);
            }
            cp_commit();
        }
        int k = 0;
        for (int J = pw; J < len; J += NPROD) {
            cp_waitg<RAWB - 1>();                 // oldest group landed
            while (J >= ld_acq(&sm_prog) + DEP) ; // eT ring backpressure
            const float* rb = myraw + k * 1024;
            float* dst = eT + (J & (DEP - 1)) * (32 * RS) + lane * RS;
            #pragma unroll
            for (int m = 0; m < 8; m++) {
                float4 v;
                v.x = ex2f(rb[(((J - 1 - (4 * m + 0)) & 31) << 5) + lane] * L2E);
                v.y = ex2f(rb[(((J - 1 - (4 * m + 1)) & 31) << 5) + lane] * L2E);
                v.z = ex2f(rb[(((J - 1 - (4 * m + 2)) & 31) << 5) + lane] * L2E);
                v.w = ex2f(rb[(((J - 1 - (4 * m + 3)) & 31) << 5) + lane] * L2E);
                *(float4*)(dst + 4 * m) = v;
            }
            st_rel(&sm_flag[J & (DEP - 1)], J);
            const int Jn = J + NPROD * RAWB;      // refill freed buffer
            if (Jn < len) {
                const float* src = lb + (size_t)Jn * 1024;
                const uint32_t d2 = rawu + (uint32_t)(k * 4096);
                #pragma unroll
                for (int c = 0; c < 8; c++)
                    cp_async16(d2 + (uint32_t)((lane + 32 * c) * 16),
                               src + (lane + 32 * c) * 4);
            }
            cp_commit();
            k = (k + 1 == RAWB) ? 0 : k + 1;
        }
        return;
    }

    // ================= scanner: warp 0 =====================================
    float E[32];
    #pragma unroll
    for (int kk = 0; kk < 32; kk++)
        E[kk] = ex2f(sm_trans[kk * 33 + lane] * L2E);
    const float end2 = end_tr[lane] * L2E;

    float R[32];
    #pragma unroll
    for (int sl = 0; sl < 31; sl++) R[sl] = 0.f;
    R[31] = ex2f(start_tr[lane] * L2E);           // start preload (rho0 = 0)

    float rho = 0.f, w = 1.f;

    for (int jb = 0; jb < len; jb += 32) {
        #pragma unroll
        for (int sl = 0; sl < 32; sl++) {
            const int j = jb + sl;
            if (j < len) {
                while (ld_acq(&sm_flag[sl & (DEP - 1)]) != j) ;
                if ((sl & 3) == 0 && j > 0) {     // epoch rescale
                    float wm = w;
                    #pragma unroll
                    for (int o = 1; o < 32; o <<= 1)
                        wm = fmaxf(wm, __shfl_xor_sync(0xffffffffu, wm, o));
                    const float delta = lg2f(wm);
                    const float f = ex2f(-delta);
                    rho += delta;
                    #pragma unroll
                    for (int kk = 0; kk < 32; kk++) R[kk] *= f;
                }
                // stage 1: w[t] = sum_sl eT[t][sl] * R[sl]
                const float* ep = eT + (sl & (DEP - 1)) * (32 * RS) + lane * RS;
                float a0 = 0.f, a1 = 0.f, a2 = 0.f, a3 = 0.f;
                #pragma unroll
                for (int m = 0; m < 8; m++) {
                    const float4 e4 = *(const float4*)(ep + 4 * m);
                    a0 = fmaf(e4.x, R[4 * m + 0], a0);
                    a1 = fmaf(e4.y, R[4 * m + 1], a1);
                    a2 = fmaf(e4.z, R[4 * m + 2], a2);
                    a3 = fmaf(e4.w, R[4 * m + 3], a3);
                }
                w = (a0 + a1) + (a2 + a3);
                // stage 2: broadcast w via smem, D[t] = sum_k w[k]*E[k]
                sm_w[lane] = w;
                __syncwarp();
                float D0 = 0.f, D1 = 0.f, D2 = 0.f, D3 = 0.f;
                #pragma unroll
                for (int m = 0; m < 8; m++) {
                    const float4 w4 = *(const float4*)(sm_w + 4 * m);
                    D0 = fmaf(w4.x, E[4 * m + 0], D0);
                    D1 = fmaf(w4.y, E[4 * m + 1], D1);
                    D2 = fmaf(w4.z, E[4 * m + 2], D2);
                    D3 = fmaf(w4.w, E[4 * m + 3], D3);
                }
                R[sl] = (D0 + D1) + (D2 + D3);
                if ((sl & 3) == 3)                // amortized progress publish
                    st_rel(&sm_prog, j + 1);
            }
        }
    }

    // ---------------- finalize ----------------
    bar2();                                       // numerator partials ready
    const float v = rho + lg2f(w) + end2;
    float m = v;
    #pragma unroll
    for (int o = 1; o < 32; o <<= 1)
        m = fmaxf(m, __shfl_xor_sync(0xffffffffu, m, o));
    float s2 = ex2f(v - m);
    #pragma unroll
    for (int o = 1; o < 32; o <<= 1)
        s2 += __shfl_xor_sync(0xffffffffu, s2, o);

    const float num = sm_num[0] + sm_num[1] + sm_num[2];
    unsigned int done = 0;
    if (lane == 0) {
        const float den = LN2f * (m + lg2f(s2));
        out[1 + b] = num;
        g_diff[b]  = num - den;
        __threadfence();
        done = (atomicAdd(&g_ctr, 1u) == 63u) ? 1u : 0u;
    }
    done = __shfl_sync(~0u, done, 0);
    if (done) {
        float x = __ldcg(&g_diff[lane]) + __ldcg(&g_diff[lane + 32]);
        #pragma unroll
        for (int o = 16; o; o >>= 1) x += __shfl_xor_sync(~0u, x, o);
        if (lane == 0) {
            out[0] = x * (1.f / 64.f);
            g_ctr = 0;
        }
    }
}

extern "C" void kernel_launch(void* const* d_in, const int* in_sizes, int n_in,
                              void* d_out, int out_size)
{
    const float* logits = (const float*)d_in[0];
    const int*   tags   = (const int*)d_in[1];
    const int*   mask   = (const int*)d_in[2];
    const float* trans  = (const float*)d_in[3];
    const float* st     = (const float*)d_in[4];
    const float* en     = (const float*)d_in[5];
    float*       out    = (float*)d_out;

    const int dyn = (DEP * 32 * RS + NPROD * RAWB * 1024) * 4;   // 171,  // bytes
    cudaFuncSetAttribute(crf_kernel, cudaFuncAttributeMaxDynamicSharedMemorySize, dyn);
    crf_kernel<<<64, 256, dyn>>>(logits, tags, mask, trans, st, en, out);
}

// round 15
// speedup vs baseline: 2.1235x; 1.1280x over previous
#include <cuda_runtime.h>
#include <cstdint>

#define L2E  1.4426950408889634f
#define LN2f 0.6931471805599453f

constexpr int S = 256, W = 32, T = 32, RS = 36;
constexpr int DEP  = 16;         // eT ring depth (tiles)
constexpr int RAWB = 8;          // raw buffers per producer warp
constexpr int NPROD = 3;         // producer warps (1..3)

typedef unsigned long long u64;

__device__ float g_diff[64];
__device__ unsigned int g_ctr = 0;

static __device__ __forceinline__ float ex2f(float x){ float y; asm("ex2.approx.ftz.f32 %0, %1;" : "=f"(y) : "f"(x)); return y; }
static __device__ __forceinline__ float lg2f(float x){ float y; asm("lg2.approx.ftz.f32 %0, %1;" : "=f"(y) : "f"(x)); return y; }

static __device__ __forceinline__ u64 pack2(float lo, float hi){
    u64 r; asm("mov.b64 %0, {%1, %2};" : "=l"(r) : "f"(lo), "f"(hi)); return r;
}
static __device__ __forceinline__ void unpack2(u64 v, float& lo, float& hi){
    asm("mov.b64 {%0, %1}, %2;" : "=f"(lo), "=f"(hi) : "l"(v));
}
static __device__ __forceinline__ void fma2(u64& acc, u64 a, u64 b){
    asm("fma.rn.f32x2 %0, %1, %2, %0;" : "+l"(acc) : "l"(a), "l"(b));
}
static __device__ __forceinline__ void mul2(u64& d, u64 a, u64 b){
    asm("mul.rn.f32x2 %0, %1, %2;" : "=l"(d) : "l"(a), "l"(b));
}

__device__ __forceinline__ void cp_async16(uint32_t dst, const float* src){
    asm volatile("cp.async.cg.shared.global [%0], [%1], 16;\n" :: "r"(dst), "l"(src));
}
__device__ __forceinline__ void cp_commit(){ asm volatile("cp.async.commit_group;\n"); }
template<int N> __device__ __forceinline__ void cp_waitg(){ asm volatile("cp.async.wait_group %0;\n" :: "n"(N)); }

__device__ __forceinline__ int ld_acq(const int* p){
    int v;
    asm volatile("ld.acquire.cta.shared.b32 %0, [%1];"
                 : "=r"(v) : "r"((uint32_t)__cvta_generic_to_shared(p)) : "memory");
    return v;
}
__device__ __forceinline__ void st_rel(int* p, int v){
    asm volatile("st.release.cta.shared.b32 [%0], %1;"
                 :: "r"((uint32_t)__cvta_generic_to_shared(p)), "r"(v) : "memory");
}

__device__ __forceinline__ void bar2(){ asm volatile("bar.sync 2, 128;" ::: "memory"); }

extern __shared__ float dynsm[];   // [DEP][32*RS] eT ring, then [NPROD][RAWB][1024] raw

__global__ __launch_bounds__(256, 1)
void crf_kernel(const float* __restrict__ logits,
                const int*   __restrict__ tags,
                const int*   __restrict__ mask,
                const float* __restrict__ trans,
                const float* __restrict__ start_tr,
                const float* __restrict__ end_tr,
                float* __restrict__ out)
{
    __shared__ float sm_trans[32 * 33];
    __shared__ __align__(16) float sm_w[32];
    __shared__ int   sm_flag[DEP];
    __shared__ int   sm_prog;
    __shared__ int   sm_ired[8];
    __shared__ float sm_num[3];

    float* eT  = dynsm;
    float* raw = dynsm + DEP * 32 * RS;

    const int b    = blockIdx.x;
    const int tid  = threadIdx.x;
    const int warp = tid >> 5, lane = tid & 31;
    const float* lb = logits + (size_t)b * S * W * T;

    for (int i = tid; i < T * T; i += 256)
        sm_trans[(i >> 5) * 33 + (i & 31)] = trans[i];
    if (tid < DEP) sm_flag[tid] = -1;
    if (tid == 0)  sm_prog = 0;
    {
        int mv = mask[b * S + tid];
        #pragma unroll
        for (int o = 16; o; o >>= 1) mv += __shfl_xor_sync(~0u, mv, o);
        if (lane == 0) sm_ired[warp] = mv;
    }
    __syncthreads();
    int len = 0;
    #pragma unroll
    for (int i = 0; i < 8; i++) len += sm_ired[i];

    if (warp == 4) return;                 // SMSP0 exclusive to scanner

    // ================= numerator: warps 5,6,7 (concurrent) =================
    if (warp >= 5) {
        const int nw = warp - 5;
        const int* tb = tags + (size_t)b * S * W;
        float acc = 0.f;
        for (int p = nw; p < len - 1; p += 3) {
            const int ptg = __ldg(&tb[p * 32 + lane]);
            float V = 0.f;
            #pragma unroll
            for (int dd = 0; dd < 32; dd++) {
                const int pt = __shfl_sync(~0u, ptg, dd);
                if (pt != 0) V += sm_trans[pt * 33 + lane];
            }
            const int j  = p + 1 + lane;
            const int jv = (j < len) ? j : (len - 1);
            const int tg = __ldg(&tb[jv * 32 + lane]);
            const float vsel = __shfl_sync(~0u, V, tg);
            float e = 0.f;
            if (tg != 0) e = __ldg(&lb[(jv * 32 + lane) * 32 + tg]);
            if (j < len) acc += vsel + e;
        }
        if (nw == 0) {
            if (lane < len) {
                const int tgd = __ldg(&tb[lane * 33]);
                acc += __ldg(&start_tr[tgd]);
                if (tgd != 0) acc += __ldg(&lb[lane * 1056 + tgd]);
            }
            const int tgl = __ldg(&tb[(len - 1) * 32 + lane]);
            if (tgl != 0) acc += __ldg(&end_tr[tgl]);
        }
        #pragma unroll
        for (int o = 16; o; o >>= 1) acc += __shfl_xor_sync(~0u, acc, o);
        if (lane == 0) sm_num[nw] = acc;
        bar2();
        return;
    }

    // ================= producers: warps 1..3 (deep free-running) ===========
    if (warp != 0) {
        const int pw = warp - 1;                  // 0..2; owns tiles pw + 3k
        float* myraw = raw + pw * (RAWB * 1024);
        const uint32_t rawu = (uint32_t)__cvta_generic_to_shared(myraw);
        #pragma unroll
        for (int k = 0; k < RAWB; k++) {
            const int Jk = pw + NPROD * k;
            if (Jk < len) {
                const float* src = lb + (size_t)Jk * 1024;
                const uint32_t dst = rawu + (uint32_t)(k * 4096);
                #pragma unroll
                for (int c = 0; c < 8; c++)
                    cp_async16(dst + (uint32_t)((lane + 32 * c) * 16),
                               src + (lane + 32 * c) * 4);
            }
            cp_commit();
        }
        int k = 0;
        for (int J = pw; J < len; J += NPROD) {
            cp_waitg<RAWB - 1>();
            while (J >= ld_acq(&sm_prog) + DEP) ;
            const float* rb = myraw + k * 1024;
            float* dst = eT + (J & (DEP - 1)) * (32 * RS) + lane * RS;
            #pragma unroll
            for (int m = 0; m < 8; m++) {
                float4 v;
                v.x = ex2f(rb[(((J - 1 - (4 * m + 0)) & 31) << 5) + lane] * L2E);
                v.y = ex2f(rb[(((J - 1 - (4 * m + 1)) & 31) << 5) + lane] * L2E);
                v.z = ex2f(rb[(((J - 1 - (4 * m + 2)) & 31) << 5) + lane] * L2E);
                v.w = ex2f(rb[(((J - 1 - (4 * m + 3)) & 31) << 5) + lane] * L2E);
                *(float4*)(dst + 4 * m) = v;
            }
            st_rel(&sm_flag[J & (DEP - 1)], J);
            const int Jn = J + NPROD * RAWB;
            if (Jn < len) {
                const float* src = lb + (size_t)Jn * 1024;
                const uint32_t d2 = rawu + (uint32_t)(k * 4096);
                #pragma unroll
                for (int c = 0; c < 8; c++)
                    cp_async16(d2 + (uint32_t)((lane + 32 * c) * 16),
                               src + (lane + 32 * c) * 4);
            }
            cp_commit();
            k = (k + 1 == RAWB) ? 0 : k + 1;
        }
        return;
    }

    // ================= scanner: warp 0 =====================================
    u64 E2[16];
    {
        float Ea[32];
        #pragma unroll
        for (int kk = 0; kk < 32; kk++)
            Ea[kk] = ex2f(sm_trans[kk * 33 + lane] * L2E);
        #pragma unroll
        for (int m = 0; m < 16; m++) E2[m] = pack2(Ea[2 * m], Ea[2 * m + 1]);
    }
    const float end2 = end_tr[lane] * L2E;

    u64 R2[16];                                  // ring: slot sl -> R2[sl/2]
    #pragma unroll
    for (int m = 0; m < 15; m++) R2[m] = pack2(0.f, 0.f);
    R2[15] = pack2(0.f, ex2f(start_tr[lane] * L2E));   // slot 31 = start

    float rho = 0.f, w, wm_saved = 1.f;

    // ---- prologue: w_0 from tile 0 against init ring ----
    while (ld_acq(&sm_flag[0]) != 0) ;
    {
        const u64* ep = (const u64*)(eT + lane * RS);
        u64 p0 = pack2(0.f, 0.f), p1 = pack2(0.f, 0.f);
        #pragma unroll
        for (int m = 0; m < 8; m++) {
            const ulonglong2 e2 = *(const ulonglong2*)(ep + 2 * m);
            fma2(p0, e2.x, R2[2 * m + 0]);
            fma2(p1, e2.y, R2[2 * m + 1]);
        }
        float x0, x1, x2, x3;
        unpack2(p0, x0, x1); unpack2(p1, x2, x3);
        w = (x0 + x1) + (x2 + x3);
    }

    // ---- main loop: iteration j computes Rn_j (stage2) and w_{j+1} ----
    for (int jb = 0; jb < len - 1; jb += 32) {
        #pragma unroll
        for (int sl = 0; sl < 32; sl++) {
            const int j = jb + sl;
            if (j < len - 1) {
                // broadcast w_j (chain head)
                sm_w[lane] = w;
                __syncwarp();
                // wait tile j+1
                while (ld_acq(&sm_flag[(j + 1) & (DEP - 1)]) != j + 1) ;
                const float* epf = eT + ((j + 1) & (DEP - 1)) * (32 * RS) + lane * RS;
                const u64*   ep  = (const u64*)epf;
                // partial over OLD ring (off the w-chain)
                u64 p0 = pack2(0.f, 0.f), p1 = pack2(0.f, 0.f);
                #pragma unroll
                for (int m = 0; m < 8; m++) {
                    const ulonglong2 e2 = *(const ulonglong2*)(ep + 2 * m);
                    fma2(p0, e2.x, R2[2 * m + 0]);
                    fma2(p1, e2.y, R2[2 * m + 1]);
                }
                float x0, x1, x2, x3;
                unpack2(p0, x0, x1); unpack2(p1, x2, x3);
                const float partial = (x0 + x1) + (x2 + x3);
                const float eTd = epf[sl];          // eT_{j+1}[t][sl_j]
                // stage 2: Rn[t] = sum_k w[k] * E[k][t]   (the chain)
                u64 d0 = pack2(0.f, 0.f), d1 = pack2(0.f, 0.f);
                #pragma unroll
                for (int m = 0; m < 8; m++) {
                    const ulonglong2 w2 = *(const ulonglong2*)(sm_w + 4 * m);
                    fma2(d0, w2.x, E2[2 * m + 0]);
                    fma2(d1, w2.y, E2[2 * m + 1]);
                }
                float y0, y1, y2, y3;
                unpack2(d0, y0, y1); unpack2(d1, y2, y3);
                const float Rn = (y0 + y1) + (y2 + y3);
                // ring slot sl update + Rold extraction (static index)
                float lo, hi;
                unpack2(R2[sl >> 1], lo, hi);
                const float Rold = (sl & 1) ? hi : lo;
                R2[sl >> 1] = (sl & 1) ? pack2(lo, Rn) : pack2(Rn, hi);
                // w_{j+1} = partial + eTd * (Rn - Rold)
                w = fmaf(eTd, Rn - Rold, partial);
                // stale max for rescale (off-chain, 3 steps of slack)
                if ((sl & 3) == 1) {
                    float t = w;
                    #pragma unroll
                    for (int o = 1; o < 32; o <<= 1)
                        t = fmaxf(t, __shfl_xor_sync(0xffffffffu, t, o));
                    wm_saved = t;
                }
                if ((sl & 3) == 3) {
                    const float delta = lg2f(wm_saved);
                    const float f = ex2f(-delta);
                    rho += delta;
                    const u64 ff = pack2(f, f);
                    #pragma unroll
                    for (int m = 0; m < 16; m++) mul2(R2[m], R2[m], ff);
                    w *= f;
                    st_rel(&sm_prog, j + 2);
                }
            }
        }
    }

    // ---------------- finalize ----------------
    bar2();                                       // numerator partials ready
    const float v = rho + lg2f(w) + end2;         // alpha_{len-1}[t]*log2e + end
    float m = v;
    #pragma unroll
    for (int o = 1; o < 32; o <<= 1)
        m = fmaxf(m, __shfl_xor_sync(0xffffffffu, m, o));
    float s2 = ex2f(v - m);
    #pragma unroll
    for (int o = 1; o < 32; o <<= 1)
        s2 += __shfl_xor_sync(0xffffffffu, s2, o);

    const float num = sm_num[0] + sm_num[1] + sm_num[2];
    unsigned int done = 0;
    if (lane == 0) {
        const float den = LN2f * (m + lg2f(s2));
        out[1 + b] = num;
        g_diff[b]  = num - den;
        __threadfence();
        done = (atomicAdd(&g_ctr, 1u) == 63u) ? 1u : 0u;
    }
    done = __shfl_sync(~0u, done, 0);
    if (done) {
        float x = __ldcg(&g_diff[lane]) + __ldcg(&g_diff[lane + 32]);
        #pragma unroll
        for (int o = 16; o; o >>= 1) x += __shfl_xor_sync(~0u, x, o);
        if (lane == 0) {
            out[0] = x * (1.f / 64.f);
            g_ctr = 0;
        }
    }
}

extern "C" void kernel_launch(void* const* d_in, const int* in_sizes, int n_in,
                              void* d_out, int out_size)
{
    const float* logits = (const float*)d_in[0];
    const int*   tags   = (const int*)d_in[1];
    const int*   mask   = (const int*)d_in[2];
    const float* trans  = (const float*)d_in[3];
    const float* st     = (const float*)d_in[4];
    const float* en     = (const float*)d_in[5];
    float*       out    = (float*)d_out;

    const int dyn = (DEP * 32 * RS + NPROD * RAWB * 1024) * 4;   // 172032 B
    cudaFuncSetAttribute(crf_kernel, cudaFuncAttributeMaxDynamicSharedMemorySize, dyn);
    crf_kernel<<<64, 256, dyn>>>(logits, tags, mask, trans, st, en, out);
}